// round 14
// baseline (speedup 1.0000x reference)
#include <cuda_runtime.h>
#include <cuda_bf16.h>
#include <math.h>
#include <stdint.h>

// ---------------------------------------------------------------------------
// SupConLossWithPrototype via mma.sync bf16, MUFU exp epilogue.
//   prep(flags+proto cvt+convert+compact+ds, 128 co-resident blocks, spin) ->
//   mma_expsum(+proto tile, +raw sums, +fused row-loss + final reduce).
// ---------------------------------------------------------------------------

#define MAXM 8192
#define NCHUNK 9
#define LOG2E5 7.2134752044448170f

__device__ __align__(16) __nv_bfloat16 d_Ahi[(size_t)MAXM * 128];
__device__ __align__(16) __nv_bfloat16 d_Bhi[(size_t)(MAXM + 128) * 128];
__device__ __align__(16) __nv_bfloat16 d_Bp[128 * 128];   // padded bf16 protos
__device__ int    d_flag[MAXM];
__device__ int    d_cnt[128];            // per-64-row novel counts
__device__ int    d_Nn;
__device__ float  d_ds[MAXM];            // |f_i|^2 (exact fp32)
__device__ float  d_Epart[(size_t)NCHUNK * MAXM];
__device__ float  d_Eraw[(size_t)NCHUNK * MAXM];
__device__ float4 d_P3[MAXM];            // (psum, pexp, bipi, -)
__device__ float  d_rowloss[MAXM];
__device__ int    d_ctrA = 0;            // prep arrive
__device__ int    d_ctrB = 0;            // prep exit
__device__ int    d_rowctr[64];          // zero-initialized
__device__ int    d_ctrF = 0;

// ------------------------------ helpers ------------------------------------

__device__ __forceinline__ uint32_t s2u(const void* p) {
    uint32_t a;
    asm("{ .reg .u64 t; cvta.to.shared.u64 t, %1; cvt.u32.u64 %0, t; }"
        : "=r"(a) : "l"(p));
    return a;
}

__device__ __forceinline__ void cp16(uint32_t s, const void* g) {
    asm volatile("cp.async.cg.shared.global [%0], [%1], 16;" :: "r"(s), "l"(g));
}
#define CP_COMMIT() asm volatile("cp.async.commit_group;" ::: "memory")

__device__ __forceinline__ void ldsm4(uint32_t (&r)[4], uint32_t addr) {
    asm volatile("ldmatrix.sync.aligned.m8n8.x4.shared.b16 {%0,%1,%2,%3}, [%4];"
                 : "=r"(r[0]), "=r"(r[1]), "=r"(r[2]), "=r"(r[3]) : "r"(addr));
}

__device__ __forceinline__ void mma16816(float (&d)[4], const uint32_t (&a)[4],
                                         uint32_t b0, uint32_t b1) {
    asm volatile(
        "mma.sync.aligned.m16n8k16.row.col.f32.bf16.bf16.f32 "
        "{%0,%1,%2,%3}, {%4,%5,%6,%7}, {%8,%9}, {%0,%1,%2,%3};"
        : "+f"(d[0]), "+f"(d[1]), "+f"(d[2]), "+f"(d[3])
        : "r"(a[0]), "r"(a[1]), "r"(a[2]), "r"(a[3]), "r"(b0), "r"(b1));
}

// XOR-swizzled smem tile: 128 rows x 256B row (16 x 16B chunks).
__device__ __forceinline__ uint32_t swz(uint32_t base, int row, int kchunk) {
    return base + row * 256 + (((uint32_t)(kchunk ^ (row & 7))) << 4);
}

__device__ __forceinline__ float ex2f(float t) {
    float r;
    asm("ex2.approx.f32 %0, %1;" : "=f"(r) : "f"(t));
    return r;
}

// exp on the FMA pipe (row-loss assembly only), rel err ~1.5e-7.
__device__ __forceinline__ float fexp(float x) {
    float t = x * 1.4426950408889634f;
    float z = t + 12582912.0f;
    int   ki = __float_as_int(z) - 0x4B400000;
    float r = t - (z - 12582912.0f);
    float p =      1.5403530393381610e-4f;
    p = fmaf(p, r, 1.3333558146428443e-3f);
    p = fmaf(p, r, 9.6181291076284772e-3f);
    p = fmaf(p, r, 5.5504108664821580e-2f);
    p = fmaf(p, r, 2.4022650695910072e-1f);
    p = fmaf(p, r, 6.9314718055994531e-1f);
    p = fmaf(p, r, 1.0f);
    return __int_as_float(__float_as_int(p) + (ki << 23));
}

// ------------------- prep: flags + proto cvt + convert ---------------------
// 128 blocks x 256 threads (all co-resident -> grid spin safe), 64 rows each.

__global__ void prep_kernel(const float* __restrict__ F,
                            const int* __restrict__ labels,
                            const int* __restrict__ plab,
                            const float* __restrict__ protos,
                            int M, int B) {
    __shared__ int sPL[128];
    __shared__ int sPos[64];
    __shared__ int sBase;
    __shared__ int sC01;
    __shared__ int sLastB;
    int tid = threadIdx.x, lane = tid & 31, w = tid >> 5;
    int blk = blockIdx.x, nblk = gridDim.x;
    int r0 = blk * 64;

    if (tid < B) sPL[tid] = plab[tid];
    __syncthreads();

    // Flags for this block's 64 rows (warps 0,1).
    int f = 0, lanePre = 0;
    if (tid < 64) {
        int lab = labels[r0 + tid];
        int hit = 0;
        #pragma unroll 4
        for (int b = 0; b < B; ++b) hit |= (lab == sPL[b]);
        f = hit ^ 1;
        d_flag[r0 + tid] = f;
        unsigned bal = __ballot_sync(0xffffffffu, f);
        lanePre = __popc(bal & ((1u << lane) - 1u));
        if (lane == 0) {
            if (w == 0) sC01 = __popc(bal);
            else atomicAdd(&sC01, 0);     // no-op placeholder (w==1 path below)
        }
    }
    __syncthreads();
    // Count for this block = popc(w0) + popc(w1); recompute cleanly:
    if (tid == 0) {
        // sC01 currently = w0 count; need total. Redo via d_flag (cheap, L1).
        int c = 0;
        #pragma unroll
        for (int q = 0; q < 64; ++q) c += d_flag[r0 + q];
        d_cnt[blk] = c;
    }

    // Block 0: proto conversion (hidden behind other blocks' flag phase).
    if (blk == 0) {
        for (int idx = tid; idx < 128 * 16; idx += 256) {
            int row = idx >> 4, kc = idx & 15;
            union { __nv_bfloat16 h[8]; uint4 u; } ph;
            if (row < B) {
                #pragma unroll
                for (int q = 0; q < 8; ++q)
                    ph.h[q] = __float2bfloat16(protos[row * 128 + kc * 8 + q]);
            } else {
                ph.u = make_uint4(0, 0, 0, 0);
            }
            ((uint4*)d_Bp)[row * 16 + kc] = ph.u;
        }
    }

    // Grid barrier: all counts visible.
    __threadfence();
    __syncthreads();
    if (tid == 0) {
        atomicAdd(&d_ctrA, 1);
        while (atomicAdd(&d_ctrA, 0) < nblk) { }
    }
    __syncthreads();
    __threadfence();

    // Prefix base over preceding 64-row chunks.
    if (w == 0) {
        int v = 0;
        #pragma unroll
        for (int q = 0; q < 4; ++q) {
            int idx = lane + q * 32;
            if (idx < blk) v += __ldcg(&d_cnt[idx]);
        }
        #pragma unroll
        for (int off = 16; off; off >>= 1)
            v += __shfl_xor_sync(0xffffffffu, v, off);
        if (lane == 0) sBase = v;
    }
    // Warp-0 count for the second 32-row half offset.
    if (tid < 64) {
        unsigned bal = __ballot_sync(0xffffffffu, f);
        if (w == 0 && lane == 0) sC01 = __popc(bal);
    }
    __syncthreads();
    if (tid < 64)
        sPos[tid] = f ? (sBase + (w ? sC01 : 0) + lanePre) : -1;
    __syncthreads();

    // Convert + compact + ds.
    int kc = tid & 15;
    #pragma unroll
    for (int sub = 0; sub < 4; ++sub) {
        int rl = sub * 16 + (tid >> 4);
        int row = r0 + rl;
        float4 v0 = *(const float4*)(F + (size_t)row * 128 + kc * 8);
        float4 v1 = *(const float4*)(F + (size_t)row * 128 + kc * 8 + 4);
        float av[8] = {v0.x, v0.y, v0.z, v0.w, v1.x, v1.y, v1.z, v1.w};
        union { __nv_bfloat16 h[8]; uint4 u; } ph;
        float dsp = 0.f;
        #pragma unroll
        for (int q = 0; q < 8; ++q) {
            ph.h[q] = __float2bfloat16(av[q]);
            dsp = fmaf(av[q], av[q], dsp);
        }
        ((uint4*)d_Ahi)[(size_t)row * 16 + kc] = ph.u;
        int p = sPos[rl];
        if (p >= 0)
            ((uint4*)d_Bhi)[(size_t)p * 16 + kc] = ph.u;
        dsp += __shfl_xor_sync(0xffffffffu, dsp, 1);
        dsp += __shfl_xor_sync(0xffffffffu, dsp, 2);
        dsp += __shfl_xor_sync(0xffffffffu, dsp, 4);
        dsp += __shfl_xor_sync(0xffffffffu, dsp, 8);
        if (kc == 0) d_ds[row] = dsp;
    }

    // Last block: Nn + B-tail pad (pad rows >= Nn, never written by others).
    if (blk == nblk - 1) {
        __shared__ int sNn;
        if (w == 0) {
            int v = 0;
            #pragma unroll
            for (int q = 0; q < 4; ++q) v += __ldcg(&d_cnt[lane + q * 32]);
            #pragma unroll
            for (int off = 16; off; off >>= 1)
                v += __shfl_xor_sync(0xffffffffu, v, off);
            if (lane == 0) { sNn = v; d_Nn = v; }
        }
        __syncthreads();
        int Nn = sNn;
        int Npad = (Nn + 127) & ~127;
        for (int idx = tid; idx < (Npad - Nn) * 16; idx += 256) {
            int row = Nn + (idx >> 4), c = idx & 15;
            ((uint4*)d_Bhi)[(size_t)row * 16 + c] = make_uint4(0, 0, 0, 0);
        }
    }

    // Exit count; last exiter resets both counters (all blocks past the spin).
    __syncthreads();
    if (tid == 0) {
        int e = atomicAdd(&d_ctrB, 1);
        if (e == nblk - 1) { d_ctrA = 0; d_ctrB = 0; }
    }
}

// ---------------------- main mma.sync exp-sum kernel -----------------------
// CTA: 128 rows x stream of 128-col novel tiles (stride NCHUNK).
// smem: A resident (32KB) + B double buffer (64KB) = 96KB; 2 CTAs/SM.
// Accumulates exp-sums AND raw dot sums. chunk-0 CTAs run the proto tile.
// Per-rowblock last-finisher assembles row losses; global last reduces.

__global__ __launch_bounds__(256, 2) void mma_expsum_kernel(
        const int* __restrict__ labels, float* __restrict__ out,
        int M, int B) {
    extern __shared__ char dyn[];
    __shared__ int sLab[128];
    const uint32_t sbase = s2u(dyn);
    const uint32_t sA = sbase;
    const uint32_t sB[2] = {sbase + 32768, sbase + 65536};

    int tid = threadIdx.x;
    int lane = tid & 31, w = tid >> 5;
    int wr = w >> 2, wc = w & 3;               // warp grid 2 x 4
    int rowbase = blockIdx.x * 128;
    int chunk = blockIdx.y;
    int Nn = d_Nn;
    int ntiles = (Nn + 127) >> 7;
    int nt = (ntiles > chunk) ? ((ntiles - chunk + NCHUNK - 1) / NCHUNK) : 0;

    // Prologue: A (group 0, with B0) + B1 (group 1).
    {
        const char* ga = (const char*)d_Ahi + (size_t)blockIdx.x * 32768;
        #pragma unroll
        for (int it = 0; it < 8; ++it) {
            int c = it * 256 + tid;
            cp16(swz(sA, c >> 4, c & 15), ga + (size_t)c * 16);
        }
        if (nt > 0) {
            const char* gb = (const char*)d_Bhi + (size_t)chunk * 32768;
            #pragma unroll
            for (int it = 0; it < 8; ++it) {
                int c = it * 256 + tid;
                cp16(swz(sB[0], c >> 4, c & 15), gb + (size_t)c * 16);
            }
        }
        CP_COMMIT();
        if (nt > 1) {
            const char* gb = (const char*)d_Bhi + (size_t)(chunk + NCHUNK) * 32768;
            #pragma unroll
            for (int it = 0; it < 8; ++it) {
                int c = it * 256 + tid;
                cp16(swz(sB[1], c >> 4, c & 15), gb + (size_t)c * 16);
            }
            CP_COMMIT();
        }
    }

    int rl = lane & 15;                 // ldmatrix row within 16-row group
    int khalf = lane >> 4;              // +1 k-chunk for upper half
    float rs[8], rw[8];
    #pragma unroll
    for (int q = 0; q < 8; ++q) { rs[q] = 0.f; rw[q] = 0.f; }

    for (int k = 0; k < nt; ++k) {
        int p = k & 1;
        if (k + 1 < nt) asm volatile("cp.async.wait_group 1;" ::: "memory");
        else            asm volatile("cp.async.wait_group 0;" ::: "memory");
        __syncthreads();

        float acc[4][4][4];
        #pragma unroll
        for (int mi = 0; mi < 4; ++mi)
            #pragma unroll
            for (int ni = 0; ni < 4; ++ni)
                #pragma unroll
                for (int q = 0; q < 4; ++q) acc[mi][ni][q] = 0.f;

        #pragma unroll
        for (int ks = 0; ks < 8; ++ks) {
            int kc = ks * 2 + khalf;
            uint32_t a[4][4], b[2][4];
            #pragma unroll
            for (int mi = 0; mi < 4; ++mi)
                ldsm4(a[mi], swz(sA, wr * 64 + mi * 16 + rl, kc));
            #pragma unroll
            for (int n2 = 0; n2 < 2; ++n2)
                ldsm4(b[n2], swz(sB[p], wc * 32 + n2 * 16 + rl, kc));
            #pragma unroll
            for (int mi = 0; mi < 4; ++mi)
                #pragma unroll
                for (int ni = 0; ni < 4; ++ni) {
                    int n2 = ni >> 1, pr = ni & 1;
                    mma16816(acc[mi][ni], a[mi], b[n2][pr], b[n2][pr + 2]);
                }
        }

        // Register-only epilogue: exp + raw sums, before the barrier.
        int cwarp = (chunk + k * NCHUNK) * 128 + wc * 32;
        if (cwarp + 32 <= Nn) {
            #pragma unroll
            for (int mi = 0; mi < 4; ++mi)
                #pragma unroll
                for (int ni = 0; ni < 4; ++ni) {
                    rs[mi * 2 + 0] += ex2f(acc[mi][ni][0] * LOG2E5) +
                                      ex2f(acc[mi][ni][1] * LOG2E5);
                    rs[mi * 2 + 1] += ex2f(acc[mi][ni][2] * LOG2E5) +
                                      ex2f(acc[mi][ni][3] * LOG2E5);
                    rw[mi * 2 + 0] += acc[mi][ni][0] + acc[mi][ni][1];
                    rw[mi * 2 + 1] += acc[mi][ni][2] + acc[mi][ni][3];
                }
        } else {
            #pragma unroll
            for (int mi = 0; mi < 4; ++mi)
                #pragma unroll
                for (int ni = 0; ni < 4; ++ni) {
                    int c0 = cwarp + ni * 8 + (lane & 3) * 2;
                    bool v0 = (c0 < Nn), v1 = (c0 + 1 < Nn);
                    float t0 = v0 ? acc[mi][ni][0] * LOG2E5 : -1e30f;
                    float t1 = v1 ? acc[mi][ni][1] * LOG2E5 : -1e30f;
                    float t2 = v0 ? acc[mi][ni][2] * LOG2E5 : -1e30f;
                    float t3 = v1 ? acc[mi][ni][3] * LOG2E5 : -1e30f;
                    rs[mi * 2 + 0] += ex2f(t0) + ex2f(t1);
                    rs[mi * 2 + 1] += ex2f(t2) + ex2f(t3);
                    if (v0) {
                        rw[mi * 2 + 0] += acc[mi][ni][0];
                        rw[mi * 2 + 1] += acc[mi][ni][2];
                    }
                    if (v1) {
                        rw[mi * 2 + 0] += acc[mi][ni][1];
                        rw[mi * 2 + 1] += acc[mi][ni][3];
                    }
                }
        }

        __syncthreads();

        if (k + 2 < nt) {                   // prefetch B(k+2) into buffer p
            const char* gb = (const char*)d_Bhi +
                             (size_t)(chunk + (k + 2) * NCHUNK) * 32768;
            #pragma unroll
            for (int it = 0; it < 8; ++it) {
                int c = it * 256 + tid;
                cp16(swz(sB[p], c >> 4, c & 15), gb + (size_t)c * 16);
            }
            CP_COMMIT();
        }
    }

    // ----------------- proto tile (chunk-0 CTAs only) ----------------------
    if (chunk == 0) {
        if (tid < 128) sLab[tid] = labels[rowbase + tid];
        {
            const char* gp = (const char*)d_Bp;
            #pragma unroll
            for (int it = 0; it < 8; ++it) {
                int c = it * 256 + tid;
                cp16(swz(sB[0], c >> 4, c & 15), gp + (size_t)c * 16);
            }
            CP_COMMIT();
        }
        asm volatile("cp.async.wait_group 0;" ::: "memory");
        __syncthreads();

        float acc[4][4][4];
        #pragma unroll
        for (int mi = 0; mi < 4; ++mi)
            #pragma unroll
            for (int ni = 0; ni < 4; ++ni)
                #pragma unroll
                for (int q = 0; q < 4; ++q) acc[mi][ni][q] = 0.f;

        #pragma unroll
        for (int ks = 0; ks < 8; ++ks) {
            int kc = ks * 2 + khalf;
            uint32_t a[4][4], b[2][4];
            #pragma unroll
            for (int mi = 0; mi < 4; ++mi)
                ldsm4(a[mi], swz(sA, wr * 64 + mi * 16 + rl, kc));
            #pragma unroll
            for (int n2 = 0; n2 < 2; ++n2)
                ldsm4(b[n2], swz(sB[0], wc * 32 + n2 * 16 + rl, kc));
            #pragma unroll
            for (int mi = 0; mi < 4; ++mi)
                #pragma unroll
                for (int ni = 0; ni < 4; ++ni) {
                    int n2 = ni >> 1, pr = ni & 1;
                    mma16816(acc[mi][ni], a[mi], b[n2][pr], b[n2][pr + 2]);
                }
        }

        float ps[8], pe[8], bi[8];
        #pragma unroll
        for (int q = 0; q < 8; ++q) { ps[q] = 0.f; pe[q] = 0.f; bi[q] = 0.f; }
        #pragma unroll
        for (int mi = 0; mi < 4; ++mi) {
            int labLo = sLab[wr * 64 + mi * 16 + (lane >> 2)];
            int labHi = sLab[wr * 64 + mi * 16 + 8 + (lane >> 2)];
            #pragma unroll
            for (int ni = 0; ni < 4; ++ni) {
                int b0 = wc * 32 + ni * 8 + (lane & 3) * 2;
                if (b0 < B) {
                    float P0 = acc[mi][ni][0] * 5.0f;
                    float P2 = acc[mi][ni][2] * 5.0f;
                    ps[mi * 2 + 0] += P0;
                    ps[mi * 2 + 1] += P2;
                    pe[mi * 2 + 0] += ex2f(acc[mi][ni][0] * LOG2E5);
                    pe[mi * 2 + 1] += ex2f(acc[mi][ni][2] * LOG2E5);
                    if (b0 == labLo) bi[mi * 2 + 0] += P0;
                    if (b0 == labHi) bi[mi * 2 + 1] += P2;
                }
                if (b0 + 1 < B) {
                    float P1 = acc[mi][ni][1] * 5.0f;
                    float P3 = acc[mi][ni][3] * 5.0f;
                    ps[mi * 2 + 0] += P1;
                    ps[mi * 2 + 1] += P3;
                    pe[mi * 2 + 0] += ex2f(acc[mi][ni][1] * LOG2E5);
                    pe[mi * 2 + 1] += ex2f(acc[mi][ni][3] * LOG2E5);
                    if (b0 + 1 == labLo) bi[mi * 2 + 0] += P1;
                    if (b0 + 1 == labHi) bi[mi * 2 + 1] += P3;
                }
            }
        }
        #pragma unroll
        for (int q = 0; q < 8; ++q) {
            ps[q] += __shfl_xor_sync(0xffffffffu, ps[q], 1);
            ps[q] += __shfl_xor_sync(0xffffffffu, ps[q], 2);
            pe[q] += __shfl_xor_sync(0xffffffffu, pe[q], 1);
            pe[q] += __shfl_xor_sync(0xffffffffu, pe[q], 2);
            bi[q] += __shfl_xor_sync(0xffffffffu, bi[q], 1);
            bi[q] += __shfl_xor_sync(0xffffffffu, bi[q], 2);
        }
        __syncthreads();
        float* sc = (float*)(dyn + 65536);   // sB[1] region as scratch
        if ((lane & 3) == 0) {
            int g = lane >> 2;
            #pragma unroll
            for (int mi = 0; mi < 4; ++mi)
                #pragma unroll
                for (int r8 = 0; r8 < 2; ++r8) {
                    int row = wr * 64 + mi * 16 + r8 * 8 + g;
                    int o = (row * 4 + wc) * 3;
                    sc[o + 0] = ps[mi * 2 + r8];
                    sc[o + 1] = pe[mi * 2 + r8];
                    sc[o + 2] = bi[mi * 2 + r8];
                }
        }
        __syncthreads();
        if (tid < 128) {
            float a = 0.f, b2 = 0.f, c2 = 0.f;
            #pragma unroll
            for (int q = 0; q < 4; ++q) {
                int o = (tid * 4 + q) * 3;
                a  += sc[o + 0];
                b2 += sc[o + 1];
                c2 += sc[o + 2];
            }
            d_P3[rowbase + tid] = make_float4(a, b2, c2, 0.f);
        }
    }

    // ---- reduce exp sums and raw sums to per-chunk row partials -----------
    #pragma unroll
    for (int q = 0; q < 8; ++q) {
        rs[q] += __shfl_xor_sync(0xffffffffu, rs[q], 1);
        rs[q] += __shfl_xor_sync(0xffffffffu, rs[q], 2);
        rw[q] += __shfl_xor_sync(0xffffffffu, rw[q], 1);
        rw[q] += __shfl_xor_sync(0xffffffffu, rw[q], 2);
    }
    __syncthreads();
    float* sred = (float*)dyn;              // 128 rows x 4 warp-cols x 2
    if ((lane & 3) == 0) {
        int g = lane >> 2;
        #pragma unroll
        for (int mi = 0; mi < 4; ++mi)
            #pragma unroll
            for (int r8 = 0; r8 < 2; ++r8) {
                int row = wr * 64 + mi * 16 + r8 * 8 + g;
                sred[(row * 4 + wc) * 2 + 0] = rs[mi * 2 + r8];
                sred[(row * 4 + wc) * 2 + 1] = rw[mi * 2 + r8];
            }
    }
    __syncthreads();
    if (tid < 128) {
        float se = 0.f, sr = 0.f;
        #pragma unroll
        for (int q = 0; q < 4; ++q) {
            se += sred[(tid * 4 + q) * 2 + 0];
            sr += sred[(tid * 4 + q) * 2 + 1];
        }
        d_Epart[(size_t)chunk * M + rowbase + tid] = se;
        d_Eraw [(size_t)chunk * M + rowbase + tid] = sr;
    }

    // ---- last chunk-CTA of this rowblock assembles row losses -------------
    __threadfence();
    __syncthreads();
    __shared__ int sFin;
    if (tid == 0)
        sFin = (atomicAdd(&d_rowctr[blockIdx.x], 1) == NCHUNK - 1);
    __syncthreads();
    if (sFin) {
        if (tid < 128) {
            int i = rowbase + tid;
            float E = 0.f, Er = 0.f;
            #pragma unroll
            for (int c = 0; c < NCHUNK; ++c) {
                E  += __ldcg(&d_Epart[(size_t)c * M + i]);
                Er += __ldcg(&d_Eraw [(size_t)c * M + i]);
            }
            float ds = __ldcg(&d_ds[i]);
            float4 p3 = __ldcg(&d_P3[i]);
            float loss;
            if (d_flag[i]) {
                float Sii = ds * 5.0f;
                float den = (E - fexp(Sii)) + p3.x;
                int cnt = Nn - 1;
                if (cnt > 0) {
                    float sumS = Er * 5.0f - Sii;
                    loss = -((sumS - logf(den) * (float)cnt) / (float)cnt);
                } else {
                    loss = 0.f;
                }
            } else {
                loss = -(p3.z - logf(E + p3.y));
            }
            d_rowloss[i] = loss;
        }
        __threadfence();
        __syncthreads();
        __shared__ int sFin2;
        if (tid == 0)
            sFin2 = (atomicAdd(&d_ctrF, 1) == (int)gridDim.x - 1);
        __syncthreads();
        if (sFin2) {
            __shared__ float sm[256];
            float s = 0.f;
            for (int r = tid; r < M; r += 256) s += __ldcg(&d_rowloss[r]);
            sm[tid] = s;
            __syncthreads();
            for (int off = 128; off; off >>= 1) {
                if (tid < off) sm[tid] += sm[tid + off];
                __syncthreads();
            }
            if (tid == 0) {
                out[0] = sm[0] / (float)M;
                d_ctrF = 0;
            }
            if (tid < 64) d_rowctr[tid] = 0;
        }
    }
}

// ------------------------------- launcher ----------------------------------

extern "C" void kernel_launch(void* const* d_in, const int* in_sizes, int n_in,
                              void* d_out, int out_size) {
    const float* F      = (const float*)d_in[0];
    const int*   labels = (const int*)d_in[1];
    const float* protos = (const float*)d_in[2];
    const int*   plab   = (const int*)d_in[3];
    int M = in_sizes[1];                  // 8192
    int B = in_sizes[3];                  // 100

    prep_kernel<<<M / 64, 256>>>(F, labels, plab, protos, M, B);

    size_t smemMain = 98304;              // 96 KB -> 2 CTAs/SM
    cudaFuncSetAttribute(mma_expsum_kernel,
                         cudaFuncAttributeMaxDynamicSharedMemorySize,
                         (int)smemMain);
    mma_expsum_kernel<<<dim3(M / 128, NCHUNK), 256, smemMain>>>(
        labels, (float*)d_out, M, B);
}

// round 16
// speedup vs baseline: 1.0763x; 1.0763x over previous
#include <cuda_runtime.h>
#include <cuda_bf16.h>
#include <math.h>
#include <stdint.h>

// ---------------------------------------------------------------------------
// SupConLossWithPrototype via mma.sync bf16, MUFU exp epilogue.
//   prep(flags+proto cvt+convert+compact+ds, 128 co-resident blocks, spin) ->
//   mma_expsum(+proto tile, +raw sums, +fused row-loss + final reduce).
//   Round 16: round-15 micro-opts with 1024-ALIGNED smem base (XOR-hoisted
//   ldsm addresses are only valid on a 256-aligned base).
// ---------------------------------------------------------------------------

#define MAXM 8192
#define NCHUNK 9
#define LOG2E5 7.2134752044448170f

__device__ __align__(16) __nv_bfloat16 d_Ahi[(size_t)MAXM * 128];
__device__ __align__(16) __nv_bfloat16 d_Bhi[(size_t)(MAXM + 128) * 128];
__device__ __align__(16) __nv_bfloat16 d_Bp[128 * 128];   // padded bf16 protos
__device__ int    d_flag[MAXM];
__device__ int    d_cnt[128];            // per-64-row novel counts
__device__ int    d_Nn;
__device__ float  d_ds[MAXM];            // |f_i|^2 (exact fp32)
__device__ float  d_Epart[(size_t)NCHUNK * MAXM];
__device__ float  d_Eraw[(size_t)NCHUNK * MAXM];
__device__ float4 d_P3[MAXM];            // (psum, pexp, bipi, -)
__device__ float  d_rowloss[MAXM];
__device__ int    d_ctrA = 0;            // prep arrive
__device__ int    d_ctrB = 0;            // prep exit
__device__ int    d_rowctr[64];          // zero-initialized
__device__ int    d_ctrF = 0;

// ------------------------------ helpers ------------------------------------

__device__ __forceinline__ uint32_t s2u(const void* p) {
    uint32_t a;
    asm("{ .reg .u64 t; cvta.to.shared.u64 t, %1; cvt.u32.u64 %0, t; }"
        : "=r"(a) : "l"(p));
    return a;
}

__device__ __forceinline__ void cp16(uint32_t s, const void* g) {
    asm volatile("cp.async.cg.shared.global [%0], [%1], 16;" :: "r"(s), "l"(g));
}
#define CP_COMMIT() asm volatile("cp.async.commit_group;" ::: "memory")

__device__ __forceinline__ void ldsm4(uint32_t (&r)[4], uint32_t addr) {
    asm volatile("ldmatrix.sync.aligned.m8n8.x4.shared.b16 {%0,%1,%2,%3}, [%4];"
                 : "=r"(r[0]), "=r"(r[1]), "=r"(r[2]), "=r"(r[3]) : "r"(addr));
}

__device__ __forceinline__ void mma16816(float (&d)[4], const uint32_t (&a)[4],
                                         uint32_t b0, uint32_t b1) {
    asm volatile(
        "mma.sync.aligned.m16n8k16.row.col.f32.bf16.bf16.f32 "
        "{%0,%1,%2,%3}, {%4,%5,%6,%7}, {%8,%9}, {%0,%1,%2,%3};"
        : "+f"(d[0]), "+f"(d[1]), "+f"(d[2]), "+f"(d[3])
        : "r"(a[0]), "r"(a[1]), "r"(a[2]), "r"(a[3]), "r"(b0), "r"(b1));
}

// XOR-swizzled smem tile: 128 rows x 256B row (16 x 16B chunks).
__device__ __forceinline__ uint32_t swz(uint32_t base, int row, int kchunk) {
    return base + row * 256 + (((uint32_t)(kchunk ^ (row & 7))) << 4);
}

// Hoisted row base (REQUIRES base % 256 == 0): addr(kc) = rbase ^ (kc<<4).
__device__ __forceinline__ uint32_t rowbase_addr(uint32_t base, int row) {
    return base + row * 256 + (((uint32_t)(row & 7)) << 4);
}

__device__ __forceinline__ float ex2f(float t) {
    float r;
    asm("ex2.approx.f32 %0, %1;" : "=f"(r) : "f"(t));
    return r;
}

// exp on the FMA pipe (row-loss assembly only), rel err ~1.5e-7.
__device__ __forceinline__ float fexp(float x) {
    float t = x * 1.4426950408889634f;
    float z = t + 12582912.0f;
    int   ki = __float_as_int(z) - 0x4B400000;
    float r = t - (z - 12582912.0f);
    float p =      1.5403530393381610e-4f;
    p = fmaf(p, r, 1.3333558146428443e-3f);
    p = fmaf(p, r, 9.6181291076284772e-3f);
    p = fmaf(p, r, 5.5504108664821580e-2f);
    p = fmaf(p, r, 2.4022650695910072e-1f);
    p = fmaf(p, r, 6.9314718055994531e-1f);
    p = fmaf(p, r, 1.0f);
    return __int_as_float(__float_as_int(p) + (ki << 23));
}

// ------------------- prep: flags + proto cvt + convert ---------------------
// 128 blocks x 256 threads (all co-resident -> grid spin safe), 64 rows each.

__global__ void prep_kernel(const float* __restrict__ F,
                            const int* __restrict__ labels,
                            const int* __restrict__ plab,
                            const float* __restrict__ protos,
                            int M, int B) {
    __shared__ int sPL[128];
    __shared__ int sPos[64];
    __shared__ int sBase;
    __shared__ int sC01;
    int tid = threadIdx.x, lane = tid & 31, w = tid >> 5;
    int blk = blockIdx.x, nblk = gridDim.x;
    int r0 = blk * 64;

    if (tid < B) sPL[tid] = plab[tid];
    __syncthreads();

    // Flags for this block's 64 rows (warps 0,1).
    int f = 0, lanePre = 0;
    if (tid < 64) {
        int lab = labels[r0 + tid];
        int hit = 0;
        #pragma unroll 4
        for (int b = 0; b < B; ++b) hit |= (lab == sPL[b]);
        f = hit ^ 1;
        d_flag[r0 + tid] = f;
        unsigned bal = __ballot_sync(0xffffffffu, f);
        lanePre = __popc(bal & ((1u << lane) - 1u));
    }
    __syncthreads();
    if (tid == 0) {
        int c = 0;
        #pragma unroll
        for (int q = 0; q < 64; ++q) c += d_flag[r0 + q];
        d_cnt[blk] = c;
    }

    // Block 0: proto conversion (hidden behind other blocks' flag phase).
    if (blk == 0) {
        for (int idx = tid; idx < 128 * 16; idx += 256) {
            int row = idx >> 4, kc = idx & 15;
            union { __nv_bfloat16 h[8]; uint4 u; } ph;
            if (row < B) {
                #pragma unroll
                for (int q = 0; q < 8; ++q)
                    ph.h[q] = __float2bfloat16(protos[row * 128 + kc * 8 + q]);
            } else {
                ph.u = make_uint4(0, 0, 0, 0);
            }
            ((uint4*)d_Bp)[row * 16 + kc] = ph.u;
        }
    }

    // Grid barrier: all counts visible.
    __threadfence();
    __syncthreads();
    if (tid == 0) {
        atomicAdd(&d_ctrA, 1);
        while (atomicAdd(&d_ctrA, 0) < nblk) { }
    }
    __syncthreads();
    __threadfence();

    // Prefix base over preceding 64-row chunks.
    if (w == 0) {
        int v = 0;
        #pragma unroll
        for (int q = 0; q < 4; ++q) {
            int idx = lane + q * 32;
            if (idx < blk) v += __ldcg(&d_cnt[idx]);
        }
        #pragma unroll
        for (int off = 16; off; off >>= 1)
            v += __shfl_xor_sync(0xffffffffu, v, off);
        if (lane == 0) sBase = v;
    }
    if (tid < 64) {
        unsigned bal = __ballot_sync(0xffffffffu, f);
        if (w == 0 && lane == 0) sC01 = __popc(bal);
    }
    __syncthreads();
    if (tid < 64)
        sPos[tid] = f ? (sBase + (w ? sC01 : 0) + lanePre) : -1;
    __syncthreads();

    // Convert + compact + ds.
    int kc = tid & 15;
    #pragma unroll
    for (int sub = 0; sub < 4; ++sub) {
        int rl = sub * 16 + (tid >> 4);
        int row = r0 + rl;
        float4 v0 = *(const float4*)(F + (size_t)row * 128 + kc * 8);
        float4 v1 = *(const float4*)(F + (size_t)row * 128 + kc * 8 + 4);
        float av[8] = {v0.x, v0.y, v0.z, v0.w, v1.x, v1.y, v1.z, v1.w};
        union { __nv_bfloat16 h[8]; uint4 u; } ph;
        float dsp = 0.f;
        #pragma unroll
        for (int q = 0; q < 8; ++q) {
            ph.h[q] = __float2bfloat16(av[q]);
            dsp = fmaf(av[q], av[q], dsp);
        }
        ((uint4*)d_Ahi)[(size_t)row * 16 + kc] = ph.u;
        int p = sPos[rl];
        if (p >= 0)
            ((uint4*)d_Bhi)[(size_t)p * 16 + kc] = ph.u;
        dsp += __shfl_xor_sync(0xffffffffu, dsp, 1);
        dsp += __shfl_xor_sync(0xffffffffu, dsp, 2);
        dsp += __shfl_xor_sync(0xffffffffu, dsp, 4);
        dsp += __shfl_xor_sync(0xffffffffu, dsp, 8);
        if (kc == 0) d_ds[row] = dsp;
    }

    // Last block: Nn + B-tail pad.
    if (blk == nblk - 1) {
        __shared__ int sNn;
        if (w == 0) {
            int v = 0;
            #pragma unroll
            for (int q = 0; q < 4; ++q) v += __ldcg(&d_cnt[lane + q * 32]);
            #pragma unroll
            for (int off = 16; off; off >>= 1)
                v += __shfl_xor_sync(0xffffffffu, v, off);
            if (lane == 0) { sNn = v; d_Nn = v; }
        }
        __syncthreads();
        int Nn = sNn;
        int Npad = (Nn + 127) & ~127;
        for (int idx = tid; idx < (Npad - Nn) * 16; idx += 256) {
            int row = Nn + (idx >> 4), c = idx & 15;
            ((uint4*)d_Bhi)[(size_t)row * 16 + c] = make_uint4(0, 0, 0, 0);
        }
    }

    __syncthreads();
    if (tid == 0) {
        int e = atomicAdd(&d_ctrB, 1);
        if (e == nblk - 1) { d_ctrA = 0; d_ctrB = 0; }
    }
}

// ---------------------- main mma.sync exp-sum kernel -----------------------
// CTA: 128 rows x stream of 128-col novel tiles (stride NCHUNK).
// smem: 1KB align pad + A (32KB) + B double buffer (64KB); 2 CTAs/SM.
// One barrier per tile: wait -> sync -> prefetch(k+1 into 1-p) -> compute(p).
// XOR-hoisted ldsm addresses on the ALIGNED base. chunk-0: proto tile.

__global__ __launch_bounds__(256, 2) void mma_expsum_kernel(
        const int* __restrict__ labels, float* __restrict__ out,
        int M, int B) {
    extern __shared__ char dyn[];
    __shared__ int sLab[128];
    const uint32_t rawb = s2u(dyn);
    const uint32_t sbase = (rawb + 1023) & ~1023u;     // 1024-aligned
    char* alg = dyn + (sbase - rawb);                  // aligned generic ptr
    const uint32_t sA = sbase;
    const uint32_t sB[2] = {sbase + 32768, sbase + 65536};

    int tid = threadIdx.x;
    int lane = tid & 31, w = tid >> 5;
    int wr = w >> 2, wc = w & 3;               // warp grid 2 x 4
    int rowbase = blockIdx.x * 128;
    int chunk = blockIdx.y;
    int Nn = d_Nn;
    int ntiles = (Nn + 127) >> 7;
    int nt = (ntiles > chunk) ? ((ntiles - chunk + NCHUNK - 1) / NCHUNK) : 0;

    // Prologue: A + B0, single commit group.
    {
        const char* ga = (const char*)d_Ahi + (size_t)blockIdx.x * 32768;
        #pragma unroll
        for (int it = 0; it < 8; ++it) {
            int c = it * 256 + tid;
            cp16(swz(sA, c >> 4, c & 15), ga + (size_t)c * 16);
        }
        if (nt > 0) {
            const char* gb = (const char*)d_Bhi + (size_t)chunk * 32768;
            #pragma unroll
            for (int it = 0; it < 8; ++it) {
                int c = it * 256 + tid;
                cp16(swz(sB[0], c >> 4, c & 15), gb + (size_t)c * 16);
            }
        }
        CP_COMMIT();
    }

    int rl = lane & 15;                 // ldmatrix row within 16-row group
    uint32_t khx = (uint32_t)(lane >> 4) << 4;   // khalf fold (bit 4)

    // Hoisted ldsm row-base addresses: addr(ks) = R ^ (ks<<5).
    uint32_t RA[4], RB[2][2];
    #pragma unroll
    for (int mi = 0; mi < 4; ++mi)
        RA[mi] = rowbase_addr(sA, wr * 64 + mi * 16 + rl) ^ khx;
    #pragma unroll
    for (int pb = 0; pb < 2; ++pb)
        #pragma unroll
        for (int n2 = 0; n2 < 2; ++n2)
            RB[pb][n2] = rowbase_addr(sB[pb], wc * 32 + n2 * 16 + rl) ^ khx;

    float rs[8], rw[8];
    #pragma unroll
    for (int q = 0; q < 8; ++q) { rs[q] = 0.f; rw[q] = 0.f; }

    for (int k = 0; k < nt; ++k) {
        int p = k & 1;
        asm volatile("cp.async.wait_group 0;" ::: "memory");
        __syncthreads();

        if (k + 1 < nt) {                   // prefetch B(k+1) into buffer 1-p
            const char* gb = (const char*)d_Bhi +
                             (size_t)(chunk + (k + 1) * NCHUNK) * 32768;
            #pragma unroll
            for (int it = 0; it < 8; ++it) {
                int c = it * 256 + tid;
                cp16(swz(sB[1 - p], c >> 4, c & 15), gb + (size_t)c * 16);
            }
            CP_COMMIT();
        }

        float acc[4][4][4];
        #pragma unroll
        for (int mi = 0; mi < 4; ++mi)
            #pragma unroll
            for (int ni = 0; ni < 4; ++ni)
                #pragma unroll
                for (int q = 0; q < 4; ++q) acc[mi][ni][q] = 0.f;

        #pragma unroll
        for (int ks = 0; ks < 8; ++ks) {
            uint32_t ko = (uint32_t)ks << 5;
            uint32_t a[4][4], b[2][4];
            #pragma unroll
            for (int mi = 0; mi < 4; ++mi)
                ldsm4(a[mi], RA[mi] ^ ko);
            #pragma unroll
            for (int n2 = 0; n2 < 2; ++n2)
                ldsm4(b[n2], RB[p][n2] ^ ko);
            #pragma unroll
            for (int mi = 0; mi < 4; ++mi)
                #pragma unroll
                for (int ni = 0; ni < 4; ++ni) {
                    int n2 = ni >> 1, pr = ni & 1;
                    mma16816(acc[mi][ni], a[mi], b[n2][pr], b[n2][pr + 2]);
                }
        }

        // Register-only epilogue: exp + raw sums.
        int cwarp = (chunk + k * NCHUNK) * 128 + wc * 32;
        if (cwarp + 32 <= Nn) {
            #pragma unroll
            for (int mi = 0; mi < 4; ++mi)
                #pragma unroll
                for (int ni = 0; ni < 4; ++ni) {
                    rs[mi * 2 + 0] += ex2f(acc[mi][ni][0] * LOG2E5) +
                                      ex2f(acc[mi][ni][1] * LOG2E5);
                    rs[mi * 2 + 1] += ex2f(acc[mi][ni][2] * LOG2E5) +
                                      ex2f(acc[mi][ni][3] * LOG2E5);
                    rw[mi * 2 + 0] += acc[mi][ni][0] + acc[mi][ni][1];
                    rw[mi * 2 + 1] += acc[mi][ni][2] + acc[mi][ni][3];
                }
        } else {
            #pragma unroll
            for (int mi = 0; mi < 4; ++mi)
                #pragma unroll
                for (int ni = 0; ni < 4; ++ni) {
                    int c0 = cwarp + ni * 8 + (lane & 3) * 2;
                    bool v0 = (c0 < Nn), v1 = (c0 + 1 < Nn);
                    float t0 = v0 ? acc[mi][ni][0] * LOG2E5 : -1e30f;
                    float t1 = v1 ? acc[mi][ni][1] * LOG2E5 : -1e30f;
                    float t2 = v0 ? acc[mi][ni][2] * LOG2E5 : -1e30f;
                    float t3 = v1 ? acc[mi][ni][3] * LOG2E5 : -1e30f;
                    rs[mi * 2 + 0] += ex2f(t0) + ex2f(t1);
                    rs[mi * 2 + 1] += ex2f(t2) + ex2f(t3);
                    if (v0) {
                        rw[mi * 2 + 0] += acc[mi][ni][0];
                        rw[mi * 2 + 1] += acc[mi][ni][2];
                    }
                    if (v1) {
                        rw[mi * 2 + 0] += acc[mi][ni][1];
                        rw[mi * 2 + 1] += acc[mi][ni][3];
                    }
                }
        }
    }

    // ----------------- proto tile (chunk-0 CTAs only) ----------------------
    if (chunk == 0) {
        if (tid < 128) sLab[tid] = labels[rowbase + tid];
        __syncthreads();                     // all warps done reading sB
        {
            const char* gp = (const char*)d_Bp;
            #pragma unroll
            for (int it = 0; it < 8; ++it) {
                int c = it * 256 + tid;
                cp16(swz(sB[0], c >> 4, c & 15), gp + (size_t)c * 16);
            }
            CP_COMMIT();
        }
        asm volatile("cp.async.wait_group 0;" ::: "memory");
        __syncthreads();

        float acc[4][4][4];
        #pragma unroll
        for (int mi = 0; mi < 4; ++mi)
            #pragma unroll
            for (int ni = 0; ni < 4; ++ni)
                #pragma unroll
                for (int q = 0; q < 4; ++q) acc[mi][ni][q] = 0.f;

        #pragma unroll
        for (int ks = 0; ks < 8; ++ks) {
            uint32_t ko = (uint32_t)ks << 5;
            uint32_t a[4][4], b[2][4];
            #pragma unroll
            for (int mi = 0; mi < 4; ++mi)
                ldsm4(a[mi], RA[mi] ^ ko);
            #pragma unroll
            for (int n2 = 0; n2 < 2; ++n2)
                ldsm4(b[n2], RB[0][n2] ^ ko);
            #pragma unroll
            for (int mi = 0; mi < 4; ++mi)
                #pragma unroll
                for (int ni = 0; ni < 4; ++ni) {
                    int n2 = ni >> 1, pr = ni & 1;
                    mma16816(acc[mi][ni], a[mi], b[n2][pr], b[n2][pr + 2]);
                }
        }

        float ps[8], pe[8], bi[8];
        #pragma unroll
        for (int q = 0; q < 8; ++q) { ps[q] = 0.f; pe[q] = 0.f; bi[q] = 0.f; }
        #pragma unroll
        for (int mi = 0; mi < 4; ++mi) {
            int labLo = sLab[wr * 64 + mi * 16 + (lane >> 2)];
            int labHi = sLab[wr * 64 + mi * 16 + 8 + (lane >> 2)];
            #pragma unroll
            for (int ni = 0; ni < 4; ++ni) {
                int b0 = wc * 32 + ni * 8 + (lane & 3) * 2;
                if (b0 < B) {
                    float P0 = acc[mi][ni][0] * 5.0f;
                    float P2 = acc[mi][ni][2] * 5.0f;
                    ps[mi * 2 + 0] += P0;
                    ps[mi * 2 + 1] += P2;
                    pe[mi * 2 + 0] += ex2f(acc[mi][ni][0] * LOG2E5);
                    pe[mi * 2 + 1] += ex2f(acc[mi][ni][2] * LOG2E5);
                    if (b0 == labLo) bi[mi * 2 + 0] += P0;
                    if (b0 == labHi) bi[mi * 2 + 1] += P2;
                }
                if (b0 + 1 < B) {
                    float P1 = acc[mi][ni][1] * 5.0f;
                    float P3 = acc[mi][ni][3] * 5.0f;
                    ps[mi * 2 + 0] += P1;
                    ps[mi * 2 + 1] += P3;
                    pe[mi * 2 + 0] += ex2f(acc[mi][ni][1] * LOG2E5);
                    pe[mi * 2 + 1] += ex2f(acc[mi][ni][3] * LOG2E5);
                    if (b0 + 1 == labLo) bi[mi * 2 + 0] += P1;
                    if (b0 + 1 == labHi) bi[mi * 2 + 1] += P3;
                }
            }
        }
        #pragma unroll
        for (int q = 0; q < 8; ++q) {
            ps[q] += __shfl_xor_sync(0xffffffffu, ps[q], 1);
            ps[q] += __shfl_xor_sync(0xffffffffu, ps[q], 2);
            pe[q] += __shfl_xor_sync(0xffffffffu, pe[q], 1);
            pe[q] += __shfl_xor_sync(0xffffffffu, pe[q], 2);
            bi[q] += __shfl_xor_sync(0xffffffffu, bi[q], 1);
            bi[q] += __shfl_xor_sync(0xffffffffu, bi[q], 2);
        }
        __syncthreads();
        float* sc = (float*)(alg + 65536);   // sB[1] region as scratch
        if ((lane & 3) == 0) {
            int g = lane >> 2;
            #pragma unroll
            for (int mi = 0; mi < 4; ++mi)
                #pragma unroll
                for (int r8 = 0; r8 < 2; ++r8) {
                    int row = wr * 64 + mi * 16 + r8 * 8 + g;
                    int o = (row * 4 + wc) * 3;
                    sc[o + 0] = ps[mi * 2 + r8];
                    sc[o + 1] = pe[mi * 2 + r8];
                    sc[o + 2] = bi[mi * 2 + r8];
                }
        }
        __syncthreads();
        if (tid < 128) {
            float a = 0.f, b2 = 0.f, c2 = 0.f;
            #pragma unroll
            for (int q = 0; q < 4; ++q) {
                int o = (tid * 4 + q) * 3;
                a  += sc[o + 0];
                b2 += sc[o + 1];
                c2 += sc[o + 2];
            }
            d_P3[rowbase + tid] = make_float4(a, b2, c2, 0.f);
        }
    }

    // ---- reduce exp sums and raw sums to per-chunk row partials -----------
    #pragma unroll
    for (int q = 0; q < 8; ++q) {
        rs[q] += __shfl_xor_sync(0xffffffffu, rs[q], 1);
        rs[q] += __shfl_xor_sync(0xffffffffu, rs[q], 2);
        rw[q] += __shfl_xor_sync(0xffffffffu, rw[q], 1);
        rw[q] += __shfl_xor_sync(0xffffffffu, rw[q], 2);
    }
    __syncthreads();
    float* sred = (float*)alg;              // 128 rows x 4 warp-cols x 2
    if ((lane & 3) == 0) {
        int g = lane >> 2;
        #pragma unroll
        for (int mi = 0; mi < 4; ++mi)
            #pragma unroll
            for (int r8 = 0; r8 < 2; ++r8) {
                int row = wr * 64 + mi * 16 + r8 * 8 + g;
                sred[(row * 4 + wc) * 2 + 0] = rs[mi * 2 + r8];
                sred[(row * 4 + wc) * 2 + 1] = rw[mi * 2 + r8];
            }
    }
    __syncthreads();
    if (tid < 128) {
        float se = 0.f, sr = 0.f;
        #pragma unroll
        for (int q = 0; q < 4; ++q) {
            se += sred[(tid * 4 + q) * 2 + 0];
            sr += sred[(tid * 4 + q) * 2 + 1];
        }
        d_Epart[(size_t)chunk * M + rowbase + tid] = se;
        d_Eraw [(size_t)chunk * M + rowbase + tid] = sr;
    }

    // ---- last chunk-CTA of this rowblock assembles row losses -------------
    __threadfence();
    __syncthreads();
    __shared__ int sFin;
    if (tid == 0)
        sFin = (atomicAdd(&d_rowctr[blockIdx.x], 1) == NCHUNK - 1);
    __syncthreads();
    if (sFin) {
        if (tid < 128) {
            int i = rowbase + tid;
            float E = 0.f, Er = 0.f;
            #pragma unroll
            for (int c = 0; c < NCHUNK; ++c) {
                E  += __ldcg(&d_Epart[(size_t)c * M + i]);
                Er += __ldcg(&d_Eraw [(size_t)c * M + i]);
            }
            float ds = __ldcg(&d_ds[i]);
            float4 p3 = __ldcg(&d_P3[i]);
            float loss;
            if (d_flag[i]) {
                float Sii = ds * 5.0f;
                float den = (E - fexp(Sii)) + p3.x;
                int cnt = Nn - 1;
                if (cnt > 0) {
                    float sumS = Er * 5.0f - Sii;
                    loss = -((sumS - logf(den) * (float)cnt) / (float)cnt);
                } else {
                    loss = 0.f;
                }
            } else {
                loss = -(p3.z - logf(E + p3.y));
            }
            d_rowloss[i] = loss;
        }
        __threadfence();
        __syncthreads();
        __shared__ int sFin2;
        if (tid == 0)
            sFin2 = (atomicAdd(&d_ctrF, 1) == (int)gridDim.x - 1);
        __syncthreads();
        if (sFin2) {
            __shared__ float sm[256];
            float s = 0.f;
            for (int r = tid; r < M; r += 256) s += __ldcg(&d_rowloss[r]);
            sm[tid] = s;
            __syncthreads();
            for (int off = 128; off; off >>= 1) {
                if (tid < off) sm[tid] += sm[tid + off];
                __syncthreads();
            }
            if (tid == 0) {
                out[0] = sm[0] / (float)M;
                d_ctrF = 0;
            }
            if (tid < 64) d_rowctr[tid] = 0;
        }
    }
}

// ------------------------------- launcher ----------------------------------

extern "C" void kernel_launch(void* const* d_in, const int* in_sizes, int n_in,
                              void* d_out, int out_size) {
    const float* F      = (const float*)d_in[0];
    const int*   labels = (const int*)d_in[1];
    const float* protos = (const float*)d_in[2];
    const int*   plab   = (const int*)d_in[3];
    int M = in_sizes[1];                  // 8192
    int B = in_sizes[3];                  // 100

    prep_kernel<<<M / 64, 256>>>(F, labels, plab, protos, M, B);

    size_t smemMain = 98304 + 1024;       // 96 KB + align pad -> 2 CTAs/SM
    cudaFuncSetAttribute(mma_expsum_kernel,
                         cudaFuncAttributeMaxDynamicSharedMemorySize,
                         (int)smemMain);
    mma_expsum_kernel<<<dim3(M / 128, NCHUNK), 256, smemMain>>>(
        labels, (float*)d_out, M, B);
}